// round 1
// baseline (speedup 1.0000x reference)
#include <cuda_runtime.h>
#include <cuda_bf16.h>
#include <math.h>

// ---------------- model constants ----------------
#define BATCH  8
#define SEQ    512
#define DMODEL 512
#define NHEAD  8
#define HEADD  64
#define FFDIM  2048
#define NLAYER 6
#define VOCAB  50257
#define BS     (BATCH*SEQ)            // 4096 rows
static const long long NLOG = (long long)BS * VOCAB;  // 205,852,672

// ---------------- device scratch (no allocations allowed) ----------------
__device__ float g_h[BS * DMODEL];
__device__ float g_xn[BS * DMODEL];
__device__ float g_q[BS * DMODEL];
__device__ float g_k[BS * DMODEL];
__device__ float g_v[BS * DMODEL];
__device__ float g_ctx[BS * DMODEL];
__device__ float g_ff[BS * FFDIM];
__device__ float g_rowloss[BS];
__device__ float g_logits_scratch[(size_t)BS * VOCAB];  // fallback if d_out is loss-only

// ---------------- helpers ----------------
// Detect whether an index array is int64 or int32 by scanning the first few
// values reinterpreted as int64: int32 data produces values >= 2^32 (the high
// word is the *next* token id, nonzero with overwhelming probability).
__device__ __forceinline__ int detect_i64(const void* p, int n) {
    const long long* x = (const long long*)p;
    int c = n < 32 ? n : 32;
    for (int i = 0; i < c; i++) {
        long long v = x[i];
        if (v < 0 || v >= VOCAB) return 0;
    }
    return 1;
}

__device__ __forceinline__ long long load_index(const void* p, int i, int is64) {
    return is64 ? ((const long long*)p)[i] : (long long)((const int*)p)[i];
}

// ---------------- embedding ----------------
__global__ __launch_bounds__(256) void embed_k(const void* __restrict__ xr,
                                               const float* __restrict__ te,
                                               const float* __restrict__ pe,
                                               float* __restrict__ h) {
    __shared__ int mode;
    if (threadIdx.x == 0) mode = detect_i64(xr, BS);
    __syncthreads();
    int pos = blockIdx.x;             // 0..BS-1
    int tid = threadIdx.x;
    long long idx = load_index(xr, pos, mode);
    int s = pos & (SEQ - 1);
    const float* t = te + idx * DMODEL;
    const float* p = pe + (long long)s * DMODEL;
    float* o = h + (long long)pos * DMODEL;
    o[tid]       = t[tid]       + p[tid];
    o[tid + 256] = t[tid + 256] + p[tid + 256];
}

// ---------------- layernorm (D=512, one block per row) ----------------
__global__ __launch_bounds__(256) void ln_k(const float* __restrict__ in,
                                            const float* __restrict__ g,
                                            const float* __restrict__ b,
                                            float* __restrict__ out) {
    int row = blockIdx.x;
    int tid = threadIdx.x;
    const float* x = in + (long long)row * DMODEL;
    float v0 = x[tid], v1 = x[tid + 256];
    __shared__ float red[256];
    red[tid] = v0 + v1;
    __syncthreads();
    #pragma unroll
    for (int s = 128; s > 0; s >>= 1) {
        if (tid < s) red[tid] += red[tid + s];
        __syncthreads();
    }
    float mu = red[0] * (1.0f / DMODEL);
    __syncthreads();
    float d0 = v0 - mu, d1 = v1 - mu;
    red[tid] = d0 * d0 + d1 * d1;
    __syncthreads();
    #pragma unroll
    for (int s = 128; s > 0; s >>= 1) {
        if (tid < s) red[tid] += red[tid + s];
        __syncthreads();
    }
    float rstd = rsqrtf(red[0] * (1.0f / DMODEL) + 1e-5f);
    float* o = out + (long long)row * DMODEL;
    o[tid]       = d0 * rstd * g[tid]       + b[tid];
    o[tid + 256] = d1 * rstd * g[tid + 256] + b[tid + 256];
}

// ---------------- tiled fp32 GEMM ----------------
// C[M,N] = op(A[M,K] @ B) (+bias) (gelu?) (+res?)
// BT=false: B is [K,N] row-major. BT=true: B is [N,K] row-major (B transposed).
// Tiles: 64x64x16, 256 threads, 4x4 per-thread microtile, float4 smem paths.
template <bool BT, bool DOGELU, bool DORES>
__global__ __launch_bounds__(256) void gemm_k(const float* __restrict__ A,
                                              const float* __restrict__ Bm,
                                              const float* __restrict__ bias,
                                              const float* __restrict__ res,
                                              float* __restrict__ C,
                                              int M, int N, int K) {
    __shared__ float As[16][68];
    __shared__ float Bs[16][68];
    const int bm = blockIdx.y * 64;
    const int bn = blockIdx.x * 64;
    const int tid = threadIdx.x;
    const int tx = tid & 15, ty = tid >> 4;

    float acc[4][4];
    #pragma unroll
    for (int i = 0; i < 4; i++)
        #pragma unroll
        for (int j = 0; j < 4; j++) acc[i][j] = 0.0f;

    const int lr = tid >> 2;          // 0..63
    const int lc = (tid & 3) * 4;     // 0,4,8,12

    for (int k0 = 0; k0 < K; k0 += 16) {
        // A tile: rows bm..bm+63 (M is a multiple of 64), cols k0+lc..+3
        float4 av = *reinterpret_cast<const float4*>(A + (long long)(bm + lr) * K + k0 + lc);
        As[lc + 0][lr] = av.x; As[lc + 1][lr] = av.y;
        As[lc + 2][lr] = av.z; As[lc + 3][lr] = av.w;
        if (BT) {
            int n = bn + lr;
            float4 bv = make_float4(0.f, 0.f, 0.f, 0.f);
            if (n < N) bv = *reinterpret_cast<const float4*>(Bm + (long long)n * K + k0 + lc);
            Bs[lc + 0][lr] = bv.x; Bs[lc + 1][lr] = bv.y;
            Bs[lc + 2][lr] = bv.z; Bs[lc + 3][lr] = bv.w;
        } else {
            int kk = tid >> 4;            // 0..15
            int n  = (tid & 15) * 4;      // 0..60
            float4 bv = *reinterpret_cast<const float4*>(Bm + (long long)(k0 + kk) * N + bn + n);
            Bs[kk][n + 0] = bv.x; Bs[kk][n + 1] = bv.y;
            Bs[kk][n + 2] = bv.z; Bs[kk][n + 3] = bv.w;
        }
        __syncthreads();
        #pragma unroll
        for (int kk = 0; kk < 16; kk++) {
            float4 a4 = *reinterpret_cast<const float4*>(&As[kk][ty * 4]);
            float4 b4 = *reinterpret_cast<const float4*>(&Bs[kk][tx * 4]);
            float a[4] = {a4.x, a4.y, a4.z, a4.w};
            float b[4] = {b4.x, b4.y, b4.z, b4.w};
            #pragma unroll
            for (int i = 0; i < 4; i++)
                #pragma unroll
                for (int j = 0; j < 4; j++) acc[i][j] = fmaf(a[i], b[j], acc[i][j]);
        }
        __syncthreads();
    }

    #pragma unroll
    for (int i = 0; i < 4; i++) {
        int row = bm + ty * 4 + i;
        #pragma unroll
        for (int j = 0; j < 4; j++) {
            int col = bn + tx * 4 + j;
            if (col < N) {
                float v = acc[i][j];
                if (bias) v += bias[col];
                if (DOGELU) v = 0.5f * v * (1.0f + erff(v * 0.70710678118654752f));
                long long off = (long long)row * N + col;
                if (DORES) v += res[off];
                C[off] = v;
            }
        }
    }
}

// ---------------- causal attention: one block per (b,h,query i) ----------------
__global__ __launch_bounds__(128) void attn_k(const float* __restrict__ q,
                                              const float* __restrict__ k,
                                              const float* __restrict__ v,
                                              float* __restrict__ ctx) {
    int gid = blockIdx.x;                 // b*H*S + h*S + i
    int i = gid & (SEQ - 1);
    int h = (gid >> 9) & (NHEAD - 1);
    int b = gid >> 12;
    int tid = threadIdx.x;

    __shared__ float shq[HEADD];
    __shared__ float sc[SEQ];
    __shared__ float red[128];

    const long long rowbase = (long long)(b * SEQ + i) * DMODEL + h * HEADD;
    if (tid < HEADD) shq[tid] = q[rowbase + tid];
    __syncthreads();

    const float inv_scale = 0.125f;   // 1/sqrt(64)
    float lmax = -1e30f;
    for (int j = tid; j <= i; j += 128) {
        const float4* kr = reinterpret_cast<const float4*>(k + (long long)(b * SEQ + j) * DMODEL + h * HEADD);
        const float4* qr = reinterpret_cast<const float4*>(shq);
        float d = 0.0f;
        #pragma unroll
        for (int c = 0; c < 16; c++) {
            float4 kv = kr[c];
            float4 qv = qr[c];
            d += qv.x * kv.x + qv.y * kv.y + qv.z * kv.z + qv.w * kv.w;
        }
        d *= inv_scale;
        sc[j] = d;
        lmax = fmaxf(lmax, d);
    }
    red[tid] = lmax;
    __syncthreads();
    #pragma unroll
    for (int s = 64; s > 0; s >>= 1) {
        if (tid < s) red[tid] = fmaxf(red[tid], red[tid + s]);
        __syncthreads();
    }
    float mx = red[0];
    __syncthreads();
    float lsum = 0.0f;
    for (int j = tid; j <= i; j += 128) {
        float e = __expf(sc[j] - mx);
        sc[j] = e;
        lsum += e;
    }
    red[tid] = lsum;
    __syncthreads();
    #pragma unroll
    for (int s = 64; s > 0; s >>= 1) {
        if (tid < s) red[tid] += red[tid + s];
        __syncthreads();
    }
    float inv_sum = 1.0f / red[0];
    __syncthreads();

    if (tid < HEADD) {
        float acc = 0.0f;
        for (int j = 0; j <= i; j++)
            acc += sc[j] * v[(long long)(b * SEQ + j) * DMODEL + h * HEADD + tid];
        ctx[rowbase + tid] = acc * inv_sum;
    }
}

// ---------------- per-row cross-entropy ----------------
__global__ __launch_bounds__(256) void loss_row_k(const float* __restrict__ logits,
                                                  const void* __restrict__ tr,
                                                  float* __restrict__ rowloss) {
    __shared__ int mode;
    __shared__ float red[256];
    int row = blockIdx.x, tid = threadIdx.x;
    if (tid == 0) mode = detect_i64(tr, BS);
    __syncthreads();
    const float* lr = logits + (long long)row * VOCAB;
    float lmax = -1e30f;
    for (int j = tid; j < VOCAB; j += 256) lmax = fmaxf(lmax, lr[j]);
    red[tid] = lmax;
    __syncthreads();
    #pragma unroll
    for (int s = 128; s > 0; s >>= 1) {
        if (tid < s) red[tid] = fmaxf(red[tid], red[tid + s]);
        __syncthreads();
    }
    float mx = red[0];
    __syncthreads();
    float lsum = 0.0f;
    for (int j = tid; j < VOCAB; j += 256) lsum += expf(lr[j] - mx);
    red[tid] = lsum;
    __syncthreads();
    #pragma unroll
    for (int s = 128; s > 0; s >>= 1) {
        if (tid < s) red[tid] += red[tid + s];
        __syncthreads();
    }
    if (tid == 0) {
        long long t = load_index(tr, row, mode);
        rowloss[row] = -(lr[t] - mx - logf(red[0]));
    }
}

__global__ __launch_bounds__(1024) void loss_reduce_k(const float* __restrict__ rowloss,
                                                      float* __restrict__ out) {
    __shared__ float red[1024];
    int tid = threadIdx.x;
    red[tid] = rowloss[tid] + rowloss[tid + 1024] + rowloss[tid + 2048] + rowloss[tid + 3072];
    __syncthreads();
    #pragma unroll
    for (int s = 512; s > 0; s >>= 1) {
        if (tid < s) red[tid] += red[tid + s];
        __syncthreads();
    }
    if (tid == 0) out[0] = red[0] * (1.0f / BS);
}

// ---------------- host launcher ----------------
extern "C" void kernel_launch(void* const* d_in, const int* in_sizes, int n_in,
                              void* d_out, int out_size) {
    (void)in_sizes; (void)n_in;
    // input order per metadata: x, targets, token_emb, pos_emb, ln1_g, ln1_b,
    // Wq, bq, Wk, bk, Wv, bv, Wo, bo, ln2_g, ln2_b, W1, b1, W2, b2, lnf_g, lnf_b
    const void*  x       = d_in[0];
    const void*  targets = d_in[1];
    const float* te   = (const float*)d_in[2];
    const float* pe   = (const float*)d_in[3];
    const float* ln1g = (const float*)d_in[4];
    const float* ln1b = (const float*)d_in[5];
    const float* Wq   = (const float*)d_in[6];
    const float* bq   = (const float*)d_in[7];
    const float* Wk   = (const float*)d_in[8];
    const float* bk   = (const float*)d_in[9];
    const float* Wv   = (const float*)d_in[10];
    const float* bv   = (const float*)d_in[11];
    const float* Wo   = (const float*)d_in[12];
    const float* bo   = (const float*)d_in[13];
    const float* ln2g = (const float*)d_in[14];
    const float* ln2b = (const float*)d_in[15];
    const float* W1   = (const float*)d_in[16];
    const float* b1   = (const float*)d_in[17];
    const float* W2   = (const float*)d_in[18];
    const float* b2   = (const float*)d_in[19];
    const float* lnfg = (const float*)d_in[20];
    const float* lnfb = (const float*)d_in[21];
    float* out = (float*)d_out;

    float *p_h, *p_xn, *p_q, *p_k, *p_v, *p_ctx, *p_ff, *p_rowloss, *p_logits;
    cudaGetSymbolAddress((void**)&p_h, g_h);
    cudaGetSymbolAddress((void**)&p_xn, g_xn);
    cudaGetSymbolAddress((void**)&p_q, g_q);
    cudaGetSymbolAddress((void**)&p_k, g_k);
    cudaGetSymbolAddress((void**)&p_v, g_v);
    cudaGetSymbolAddress((void**)&p_ctx, g_ctx);
    cudaGetSymbolAddress((void**)&p_ff, g_ff);
    cudaGetSymbolAddress((void**)&p_rowloss, g_rowloss);
    cudaGetSymbolAddress((void**)&p_logits, g_logits_scratch);

    embed_k<<<BS, 256>>>(x, te, pe, p_h);

    dim3 gDD(DMODEL / 64, BS / 64);   // (8,64)
    dim3 gDF(FFDIM / 64, BS / 64);    // (32,64)

    for (int l = 0; l < NLAYER; l++) {
        long long oDD = (long long)l * DMODEL * DMODEL;
        long long oDF = (long long)l * DMODEL * FFDIM;
        ln_k<<<BS, 256>>>(p_h, ln1g + l * DMODEL, ln1b + l * DMODEL, p_xn);
        gemm_k<false, false, false><<<gDD, 256>>>(p_xn, Wq + oDD, bq + l * DMODEL, nullptr, p_q, BS, DMODEL, DMODEL);
        gemm_k<false, false, false><<<gDD, 256>>>(p_xn, Wk + oDD, bk + l * DMODEL, nullptr, p_k, BS, DMODEL, DMODEL);
        gemm_k<false, false, false><<<gDD, 256>>>(p_xn, Wv + oDD, bv + l * DMODEL, nullptr, p_v, BS, DMODEL, DMODEL);
        attn_k<<<BATCH * NHEAD * SEQ, 128>>>(p_q, p_k, p_v, p_ctx);
        gemm_k<false, false, true><<<gDD, 256>>>(p_ctx, Wo + oDD, bo + l * DMODEL, p_h, p_h, BS, DMODEL, DMODEL);
        ln_k<<<BS, 256>>>(p_h, ln2g + l * DMODEL, ln2b + l * DMODEL, p_xn);
        gemm_k<false, true, false><<<gDF, 256>>>(p_xn, W1 + oDF, b1 + l * FFDIM, nullptr, p_ff, BS, FFDIM, DMODEL);
        gemm_k<false, false, true><<<gDD, 256>>>(p_ff, W2 + oDF, b2 + l * DMODEL, p_h, p_h, BS, DMODEL, FFDIM);
    }

    ln_k<<<BS, 256>>>(p_h, lnfg, lnfb, p_xn);

    float* logits = ((long long)out_size >= NLOG) ? out : p_logits;
    dim3 gLOG((VOCAB + 63) / 64, BS / 64);
    gemm_k<true, false, false><<<gLOG, 256>>>(p_xn, te, nullptr, nullptr, logits, BS, VOCAB, DMODEL);

    loss_row_k<<<BS, 256>>>(logits, targets, p_rowloss);
    if ((long long)out_size > NLOG) {
        loss_reduce_k<<<1, 1024>>>(p_rowloss, out + NLOG);
    } else if ((long long)out_size < NLOG && out_size >= 1) {
        loss_reduce_k<<<1, 1024>>>(p_rowloss, out + (out_size - 1));
    }
}

// round 3
// speedup vs baseline: 1.8155x; 1.8155x over previous
#include <cuda_runtime.h>
#include <cuda_bf16.h>
#include <math.h>
#include <stdint.h>

// ---------------- model constants ----------------
#define BATCH  8
#define SEQ    512
#define DMODEL 512
#define NHEAD  8
#define HEADD  64
#define FFDIM  2048
#define NLAYER 6
#define VOCAB  50257
#define VPAD   50304                  // 393*128
#define BS     (BATCH*SEQ)            // 4096 rows
static const long long NLOG = (long long)BS * VOCAB;  // 205,852,672

// converted-weight layout (bf16), per layer:
//  [q_hi q_lo k_hi k_lo v_hi v_lo o_hi o_lo] each 512*512, then W1_hi W1_lo (512*2048 -> [F,D]), W2_hi W2_lo ([D,F])
#define DDSZ   (DMODEL*DMODEL)                 // 262144
#define DFSZ   (DMODEL*FFDIM)                  // 1048576
#define QKVO_TOT (4*2*DDSZ)                    // 2097152
#define WL_STRIDE (QKVO_TOT + 2*DFSZ + 2*DFSZ) // 6291456

// ---------------- device scratch ----------------
__device__ float g_h[BS * DMODEL];
__device__ float g_q[BS * DMODEL];
__device__ float g_k[BS * DMODEL];
__device__ float g_v[BS * DMODEL];
__device__ float g_rowloss[BS];
__device__ float g_logits_scratch[(size_t)BS * VOCAB];
__device__ __nv_bfloat16 g_xnh[BS * DMODEL];
__device__ __nv_bfloat16 g_xnl[BS * DMODEL];
__device__ __nv_bfloat16 g_ctxh[BS * DMODEL];
__device__ __nv_bfloat16 g_ctxl[BS * DMODEL];
__device__ __nv_bfloat16 g_ffh[BS * FFDIM];
__device__ __nv_bfloat16 g_ffl[BS * FFDIM];
__device__ __nv_bfloat16 g_wbuf[(size_t)WL_STRIDE * NLAYER];
__device__ __nv_bfloat16 g_emb[2 * (size_t)VPAD * DMODEL];   // hi at 0, lo at VPAD*D

// ================= common PTX helpers =================
__device__ __forceinline__ uint32_t smem_to_u32(const void* smem_ptr) {
    uint32_t addr;
    asm("{ .reg .u64 tmp; cvta.to.shared.u64 tmp, %1; cvt.u32.u64 %0, tmp; }"
        : "=r"(addr) : "l"(smem_ptr));
    return addr;
}
__device__ __forceinline__ void cp16(uint32_t d, const void* s, int sz) {
    asm volatile("cp.async.cg.shared.global [%0], [%1], 16, %2;\n"
                 :: "r"(d), "l"(s), "r"(sz) : "memory");
}
__device__ __forceinline__ void cp_commit() {
    asm volatile("cp.async.commit_group;\n" ::: "memory");
}
__device__ __forceinline__ void cp_wait0() {
    asm volatile("cp.async.wait_group 0;\n" ::: "memory");
}
__device__ __forceinline__ void cp_wait1() {
    asm volatile("cp.async.wait_group 1;\n" ::: "memory");
}
#define LDSM4(r, addr) \
    asm volatile("ldmatrix.sync.aligned.m8n8.x4.shared.b16 {%0,%1,%2,%3}, [%4];" \
        : "=r"((r)[0]), "=r"((r)[1]), "=r"((r)[2]), "=r"((r)[3]) : "r"(addr))
#define MMA16816(c, a, b0, b1) \
    asm volatile("mma.sync.aligned.m16n8k16.row.col.f32.bf16.bf16.f32 " \
        "{%0,%1,%2,%3}, {%4,%5,%6,%7}, {%8,%9}, {%0,%1,%2,%3};" \
        : "+f"((c)[0]), "+f"((c)[1]), "+f"((c)[2]), "+f"((c)[3]) \
        : "r"((a)[0]), "r"((a)[1]), "r"((a)[2]), "r"((a)[3]), "r"(b0), "r"(b1))

// ---- tcgen05 helpers (only referenced when __CUDA_ARCH_FEAT_SM103_ALL) ----
#if defined(__CUDA_ARCH_FEAT_SM103_ALL)
__device__ __forceinline__ uint32_t elect_one_pred() {
    uint32_t pred;
    asm volatile("{\n\t.reg .pred p;\n\telect.sync _|p, 0xFFFFFFFF;\n\tselp.b32 %0, 1, 0, p;\n\t}"
        : "=r"(pred));
    return pred;
}
#define MBARRIER_INIT(mbar, count) \
    asm volatile("mbarrier.init.shared.b64 [%0], %1;" :: "r"((uint32_t)(mbar)), "r"((uint32_t)(count)) : "memory")
#define MBARRIER_WAIT_PARITY(mbar_smem_addr, phase_parity) do { \
    uint32_t _mbar = (uint32_t)(mbar_smem_addr); \
    uint32_t _parity = (uint32_t)(phase_parity); \
    uint32_t _done; \
    asm volatile("{\n\t.reg .pred p;\n\t" \
        "mbarrier.try_wait.parity.acquire.cta.shared::cta.b64 p, [%1], %2;\n\t" \
        "selp.b32 %0, 1, 0, p;\n\t}" \
        : "=r"(_done) : "r"(_mbar), "r"(_parity) : "memory"); \
    if (!_done) { \
        asm volatile("{\n\t.reg .pred P1;\n\t" \
            "WAIT_LOOP_%=:\n\t" \
            "mbarrier.try_wait.parity.acquire.cta.shared::cta.b64 P1, [%0], %1, 0x989680;\n\t" \
            "@P1 bra.uni WAIT_DONE_%=;\n\t" \
            "bra.uni WAIT_LOOP_%=;\n\t" \
            "WAIT_DONE_%=:\n\t}" \
            :: "r"(_mbar), "r"(_parity) : "memory"); \
    } \
} while(0)
#define TCGEN05_ALLOC(sra, nCols) \
    asm volatile("tcgen05.alloc.cta_group::1.sync.aligned.shared::cta.b32 [%0], %1;" \
        :: "r"((uint32_t)(sra)), "r"((uint32_t)(nCols)) : "memory")
#define TCGEN05_DEALLOC(tmem_addr, nCols) \
    asm volatile("tcgen05.dealloc.cta_group::1.sync.aligned.b32 %0, %1;" \
        :: "r"(tmem_addr), "r"((uint32_t)(nCols)))
#define TCGEN05_RELINQUISH() \
    asm volatile("tcgen05.relinquish_alloc_permit.cta_group::1.sync.aligned;")
#define TCGEN05_COMMIT(mbar) \
    asm volatile("tcgen05.commit.cta_group::1.mbarrier::arrive::one.shared::cluster.b64 [%0];" \
        :: "r"((uint32_t)(mbar)) : "memory")
#define TCGEN05_WAIT_LD() asm volatile("tcgen05.wait::ld.sync.aligned;" ::: "memory")
#define TCGEN05_FENCE_AFTER() asm volatile("tcgen05.fence::after_thread_sync;" ::: "memory")
#define TCGEN05_LD_32X32B_X32(r, tmem_addr) \
    asm volatile( \
        "tcgen05.ld.sync.aligned.32x32b.x32.b32 " \
        "{%0, %1, %2, %3, %4, %5, %6, %7, " \
        " %8, %9, %10, %11, %12, %13, %14, %15, " \
        " %16, %17, %18, %19, %20, %21, %22, %23, " \
        " %24, %25, %26, %27, %28, %29, %30, %31}, [%32];" \
        : "=r"((r)[0]),  "=r"((r)[1]),  "=r"((r)[2]),  "=r"((r)[3]), \
          "=r"((r)[4]),  "=r"((r)[5]),  "=r"((r)[6]),  "=r"((r)[7]), \
          "=r"((r)[8]),  "=r"((r)[9]),  "=r"((r)[10]), "=r"((r)[11]), \
          "=r"((r)[12]), "=r"((r)[13]), "=r"((r)[14]), "=r"((r)[15]), \
          "=r"((r)[16]), "=r"((r)[17]), "=r"((r)[18]), "=r"((r)[19]), \
          "=r"((r)[20]), "=r"((r)[21]), "=r"((r)[22]), "=r"((r)[23]), \
          "=r"((r)[24]), "=r"((r)[25]), "=r"((r)[26]), "=r"((r)[27]), \
          "=r"((r)[28]), "=r"((r)[29]), "=r"((r)[30]), "=r"((r)[31]) \
        : "r"(tmem_addr))
static constexpr uint64_t SMEM_DESC_BASE_SW128 =
    (uint64_t(2) << 61) | (uint64_t(1) << 46) | (uint64_t(64) << 32) | (uint64_t(1) << 16);
#define MAKE_SMEM_DESC(base_addr) (SMEM_DESC_BASE_SW128 | ((uint64_t)((base_addr) >> 4) & 0x3FFF))
__device__ __forceinline__ void mma_f16_ss(uint32_t d, uint64_t ad, uint64_t bd,
                                           uint32_t idesc, uint32_t en) {
    asm volatile("{\n\t.reg .pred p;\n\tsetp.ne.u32 p, %4, 0;\n\t"
        "tcgen05.mma.cta_group::1.kind::f16 [%0], %1, %2, %3, {%5, %5, %5, %5}, p;\n\t}"
        :: "r"(d), "l"(ad), "l"(bd), "r"(idesc), "r"(en), "r"(0u) : "memory");
}
static constexpr uint32_t GEMM_IDESC =
    (1u << 4) | (1u << 7) | (1u << 10) | ((128u / 8) << 17) | ((128u / 16) << 24);
#endif

// ---------------- GEMM smem layout ----------------
// stage: [Ahi 16K][Alo 16K][Bhi 16K][Blo 16K]; tiles are 128 rows x 64 bf16 (128B rows, xor-swizzled)
#define TB 16384
#define STAGE_BYTES (4*TB)
#define SMEM_OFF 1024
#define GEMM_SMEM (SMEM_OFF + 2*STAGE_BYTES)   // 132096

// stage copy: A[M,K] hi/lo bf16 K-major, B[N,K] hi/lo bf16 K-major. 64-k chunk.
__device__ __forceinline__ void copy_stage(uint32_t st,
        const __nv_bfloat16* __restrict__ Ahi, const __nv_bfloat16* __restrict__ Alo,
        const __nv_bfloat16* __restrict__ Bhi, const __nv_bfloat16* __restrict__ Blo,
        int bm, int bn, int k0, int K, int N, int tid) {
    #pragma unroll
    for (int it = 0; it < 4; it++) {
        int idx = tid + it * 256;
        int row = idx >> 3, c = idx & 7;
        uint32_t d = st + row * 128 + ((c ^ (row & 7)) << 4);
        size_t so = (size_t)(bm + row) * K + k0 + c * 8;
        cp16(d, Ahi + so, 16);
        cp16(d + TB, Alo + so, 16);
    }
    #pragma unroll
    for (int it = 0; it < 4; it++) {
        int idx = tid + it * 256;
        int row = idx >> 3, c = idx & 7;
        int n = bn + row;
        int sz = (n < N) ? 16 : 0;
        uint32_t d = st + 2 * TB + row * 128 + ((c ^ (row & 7)) << 4);
        size_t so = (size_t)n * K + k0 + c * 8;
        cp16(d, Bhi + so, sz);
        cp16(d + TB, Blo + so, sz);
    }
}

// epilogue op: 0=bias->f32, 1=bias+res->f32, 2=bias+gelu->bf16 split, 3=plain f32
template <int EPI>
__device__ __forceinline__ void emit_one(float x, size_t off, int col,
        const float* __restrict__ bias, const float* __restrict__ res,
        float* __restrict__ C, __nv_bfloat16* __restrict__ Chi, __nv_bfloat16* __restrict__ Clo) {
    if (EPI == 0 || EPI == 1 || EPI == 2) x += __ldg(bias + col);
    if (EPI == 2) x = 0.5f * x * (1.0f + erff(x * 0.70710678118654752440f));
    if (EPI == 1) x += res[off];
    if (EPI == 2) {
        __nv_bfloat16 h = __float2bfloat16(x);
        Chi[off] = h;
        Clo[off] = __float2bfloat16(x - __bfloat162float(h));
    } else {
        C[off] = x;
    }
}

// ---------------- GEMM kernel: C[M,N] = (Ahi+Alo)(Bhi+Blo)^T (split-compensated) ----------------
template <int EPI>
__global__ void __launch_bounds__(256, 1)
gemm_bf(const __nv_bfloat16* __restrict__ Ahi, const __nv_bfloat16* __restrict__ Alo,
        const __nv_bfloat16* __restrict__ Bhi, const __nv_bfloat16* __restrict__ Blo,
        const float* __restrict__ bias, const float* __restrict__ res,
        float* __restrict__ C, __nv_bfloat16* __restrict__ Chi, __nv_bfloat16* __restrict__ Clo,
        int M, int N, int K) {
    extern __shared__ char smem[];
    const int tid = threadIdx.x;
    const int bm = blockIdx.x * 128;
    const int bn = blockIdx.y * 128;
    const int nc = K >> 6;

#if defined(__CUDA_ARCH_FEAT_SM103_ALL)
    // ================= tcgen05 path (sm_103a cubin only) =================
    const uint32_t hb = smem_to_u32(smem);
    const uint32_t tiles = hb + SMEM_OFF;
    if (tid < 32) TCGEN05_ALLOC(hb, 128);
    if (tid == 0) { MBARRIER_INIT(hb + 8, 1); MBARRIER_INIT(hb + 16, 1); }
    __syncthreads();
    if (tid < 32) TCGEN05_RELINQUISH();
    uint32_t tmem;
    asm volatile("ld.shared.b32 %0, [%1];" : "=r"(tmem) : "r"(hb));

    for (int c = 0; c < nc; c++) {
        const int buf = c & 1;
        const uint32_t st = tiles + buf * STAGE_BYTES;
        const uint32_t mb = hb + 8 + buf * 8;
        if (c >= 2) { MBARRIER_WAIT_PARITY(mb, ((c - 2) >> 1) & 1); }
        copy_stage(st, Ahi, Alo, Bhi, Blo, bm, bn, c << 6, K, N, tid);
        cp_commit();
        cp_wait0();
        __syncthreads();
        asm volatile("fence.proxy.async.shared::cta;" ::: "memory");
        if (tid < 32) {
            if (elect_one_pred()) {
                uint64_t dA  = MAKE_SMEM_DESC(st);
                uint64_t dAl = MAKE_SMEM_DESC(st + TB);
                uint64_t dB  = MAKE_SMEM_DESC(st + 2 * TB);
                uint64_t dBl = MAKE_SMEM_DESC(st + 3 * TB);
                #pragma unroll
                for (int s = 0; s < 4; s++)
                    mma_f16_ss(tmem, dA + s * 2, dB + s * 2, GEMM_IDESC, (c > 0) | (s > 0));
                #pragma unroll
                for (int s = 0; s < 4; s++)
                    mma_f16_ss(tmem, dAl + s * 2, dB + s * 2, GEMM_IDESC, 1u);
                #pragma unroll
                for (int s = 0; s < 4; s++)
                    mma_f16_ss(tmem, dA + s * 2, dBl + s * 2, GEMM_IDESC, 1u);
                TCGEN05_COMMIT(mb);
            }
        }
    }
    {
        int u0 = (nc + 1) >> 1, u1 = nc >> 1;
        MBARRIER_WAIT_PARITY(hb + 8, (u0 - 1) & 1);
        if (u1 > 0) MBARRIER_WAIT_PARITY(hb + 16, (u1 - 1) & 1);
    }
    TCGEN05_FENCE_AFTER();
    if (tid < 128) {
        uint32_t dreg[128];
        TCGEN05_LD_32X32B_X32(dreg, tmem);
        TCGEN05_LD_32X32B_X32(dreg + 32, tmem + 32);
        TCGEN05_LD_32X32B_X32(dreg + 64, tmem + 64);
        TCGEN05_LD_32X32B_X32(dreg + 96, tmem + 96);
        TCGEN05_WAIT_LD();
        int row = bm + tid;
        size_t base = (size_t)row * N;
        #pragma unroll 8
        for (int c0 = 0; c0 < 128; c0++) {
            int col = bn + c0;
            if (col < N)
                emit_one<EPI>(__uint_as_float(dreg[c0]), base + col, col, bias, res, C, Chi, Clo);
        }
    }
    __syncthreads();
    if (tid < 32) TCGEN05_DEALLOC(tmem, 128);
#else
    // ================= mma.sync fallback (plain sm_103) =================
    const uint32_t tiles = smem_to_u32(smem) + SMEM_OFF;
    const int lane = tid & 31;
    const int wid = tid >> 5;
    const int wm = (wid & 3) << 5;     // warp m-offset (32 rows)
    const int wn = (wid >> 2) << 6;    // warp n-offset (64 cols)
    const int mi = lane >> 3;          // ldmatrix matrix id 0..3
    const int lrow = lane & 7;

    float acc[2][8][4];
    #pragma unroll
    for (int i = 0; i < 2; i++)
        #pragma unroll
        for (int j = 0; j < 8; j++)
            #pragma unroll
            for (int t = 0; t < 4; t++) acc[i][j][t] = 0.0f;

    copy_stage(tiles, Ahi, Alo, Bhi, Blo, bm, bn, 0, K, N, tid);
    cp_commit();

    for (int c = 0; c < nc; c++) {
        if (c + 1 < nc) {
            copy_stage(tiles + ((c + 1) & 1) * STAGE_BYTES, Ahi, Alo, Bhi, Blo,
                       bm, bn, (c + 1) << 6, K, N, tid);
            cp_commit();
            cp_wait1();
        } else {
            cp_wait0();
        }
        __syncthreads();

        const uint32_t st = tiles + (c & 1) * STAGE_BYTES;
        #pragma unroll
        for (int s = 0; s < 4; s++) {
            const int cb = (s << 5) + ((mi >> 1) << 4);   // byte offset within row
            uint32_t ahi[2][4], alo[2][4], bhi[4][4], blo[4][4];
            #pragma unroll
            for (int i = 0; i < 2; i++) {
                int r = wm + (i << 4) + ((mi & 1) << 3) + lrow;
                uint32_t a = st + r * 128 + (cb ^ ((r & 7) << 4));
                LDSM4(ahi[i], a);
                LDSM4(alo[i], a + TB);
            }
            #pragma unroll
            for (int j2 = 0; j2 < 4; j2++) {
                int r = wn + (j2 << 4) + ((mi & 1) << 3) + lrow;
                uint32_t a = st + 2 * TB + r * 128 + (cb ^ ((r & 7) << 4));
                LDSM4(bhi[j2], a);
                LDSM4(blo[j2], a + TB);
            }
            // pass 1: Ahi * Bhi ; pass 2: Alo * Bhi ; pass 3: Ahi * Blo
            #pragma unroll
            for (int i = 0; i < 2; i++)
                #pragma unroll
                for (int j2 = 0; j2 < 4; j2++) {
                    MMA16816(acc[i][2 * j2],     ahi[i], bhi[j2][0], bhi[j2][2]);
                    MMA16816(acc[i][2 * j2 + 1], ahi[i], bhi[j2][1], bhi[j2][3]);
                }
            #pragma unroll
            for (int i = 0; i < 2; i++)
                #pragma unroll
                for (int j2 = 0; j2 < 4; j2++) {
                    MMA16816(acc[i][2 * j2],     alo[i], bhi[j2][0], bhi[j2][2]);
                    MMA16816(acc[i][2 * j2 + 1], alo[i], bhi[j2][1], bhi[j2][3]);
                }
            #pragma unroll
            for (int i = 0; i < 2; i++)
                #pragma unroll
                for (int j2 = 0; j2 < 4; j2++) {
                    MMA16816(acc[i][2 * j2],     ahi[i], blo[j2][0], blo[j2][2]);
                    MMA16816(acc[i][2 * j2 + 1], ahi[i], blo[j2][1], blo[j2][3]);
                }
        }
        __syncthreads();
    }

    // epilogue
    #pragma unroll
    for (int i = 0; i < 2; i++) {
        int row = bm + wm + (i << 4) + (lane >> 2);
        size_t base = (size_t)row * N;
        size_t base8 = base + (size_t)8 * N;
        #pragma unroll
        for (int j = 0; j < 8; j++) {
            int col = bn + wn + (j << 3) + ((lane & 3) << 1);
            if (col < N)     emit_one<EPI>(acc[i][j][0], base + col, col, bias, res, C, Chi, Clo);
            if (col + 1 < N) emit_one<EPI>(acc[i][j][1], base + col + 1, col + 1, bias, res, C, Chi, Clo);
            if (col < N)     emit_one<EPI>(acc[i][j][2], base8 + col, col, bias, res, C, Chi, Clo);
            if (col + 1 < N) emit_one<EPI>(acc[i][j][3], base8 + col + 1, col + 1, bias, res, C, Chi, Clo);
        }
    }
#endif
}

// ---------------- weight transpose + split kernels ----------------
__device__ __forceinline__ void transpose_split(const float* __restrict__ in,
        __nv_bfloat16* __restrict__ hi, __nv_bfloat16* __restrict__ lo, int K, int N) {
    __shared__ float t[32][33];
    int n0 = blockIdx.x << 5, k0 = blockIdx.y << 5;
    int tx = threadIdx.x, ty = threadIdx.y;   // (32, 8)
    #pragma unroll
    for (int r = 0; r < 4; r++)
        t[ty + 8 * r][tx] = in[(size_t)(k0 + ty + 8 * r) * N + n0 + tx];
    __syncthreads();
    #pragma unroll
    for (int r = 0; r < 4; r++) {
        float v = t[tx][ty + 8 * r];
        size_t o = (size_t)(n0 + ty + 8 * r) * K + k0 + tx;
        __nv_bfloat16 h = __float2bfloat16(v);
        hi[o] = h;
        lo[o] = __float2bfloat16(v - __bfloat162float(h));
    }
}
__global__ void wsplit_qkvo_k(const float* __restrict__ Wq, const float* __restrict__ Wk,
                              const float* __restrict__ Wv, const float* __restrict__ Wo,
                              __nv_bfloat16* __restrict__ wbuf) {
    int z = blockIdx.z, l = z >> 2, m = z & 3;
    const float* W = (m == 0 ? Wq : m == 1 ? Wk : m == 2 ? Wv : Wo) + (size_t)l * DDSZ;
    __nv_bfloat16* hi = wbuf + (size_t)l * WL_STRIDE + (size_t)m * 2 * DDSZ;
    transpose_split(W, hi, hi + DDSZ, DMODEL, DMODEL);
}
__global__ void wsplit_w1_k(const float* __restrict__ W1, __nv_bfloat16* __restrict__ wbuf) {
    int l = blockIdx.z;
    __nv_bfloat16* hi = wbuf + (size_t)l * WL_STRIDE + QKVO_TOT;
    transpose_split(W1 + (size_t)l * DFSZ, hi, hi + DFSZ, DMODEL, FFDIM);
}
__global__ void wsplit_w2_k(const float* __restrict__ W2, __nv_bfloat16* __restrict__ wbuf) {
    int l = blockIdx.z;
    __nv_bfloat16* hi = wbuf + (size_t)l * WL_STRIDE + QKVO_TOT + 2 * (size_t)DFSZ;
    transpose_split(W2 + (size_t)l * DFSZ, hi, hi + DFSZ, FFDIM, DMODEL);
}
__global__ __launch_bounds__(256) void embsplit_k(const float* __restrict__ te,
        __nv_bfloat16* __restrict__ hi, __nv_bfloat16* __restrict__ lo) {
    size_t n = (size_t)VOCAB * DMODEL;
    for (size_t i = (size_t)blockIdx.x * blockDim.x + threadIdx.x; i < n;
         i += (size_t)gridDim.x * blockDim.x) {
        float v = te[i];
        __nv_bfloat16 h = __float2bfloat16(v);
        hi[i] = h;
        lo[i] = __float2bfloat16(v - __bfloat162float(h));
    }
}

// ---------------- helpers ----------------
__device__ __forceinline__ int detect_i64(const void* p, int n) {
    const long long* x = (const long long*)p;
    int c = n < 32 ? n : 32;
    for (int i = 0; i < c; i++) {
        long long v = x[i];
        if (v < 0 || v >= VOCAB) return 0;
    }
    return 1;
}
__device__ __forceinline__ long long load_index(const void* p, int i, int is64) {
    return is64 ? ((const long long*)p)[i] : (long long)((const int*)p)[i];
}

// ---------------- embedding ----------------
__global__ __launch_bounds__(256) void embed_k(const void* __restrict__ xr,
                                               const float* __restrict__ te,
                                               const float* __restrict__ pe,
                                               float* __restrict__ h) {
    __shared__ int mode;
    if (threadIdx.x == 0) mode = detect_i64(xr, BS);
    __syncthreads();
    int pos = blockIdx.x;
    int tid = threadIdx.x;
    long long idx = load_index(xr, pos, mode);
    int s = pos & (SEQ - 1);
    const float* t = te + idx * DMODEL;
    const float* p = pe + (long long)s * DMODEL;
    float* o = h + (long long)pos * DMODEL;
    o[tid]       = t[tid]       + p[tid];
    o[tid + 256] = t[tid + 256] + p[tid + 256];
}

// ---------------- layernorm -> bf16 split ----------------
__global__ __launch_bounds__(256) void ln_k(const float* __restrict__ in,
                                            const float* __restrict__ g,
                                            const float* __restrict__ b,
                                            __nv_bfloat16* __restrict__ oh,
                                            __nv_bfloat16* __restrict__ ol) {
    int row = blockIdx.x;
    int tid = threadIdx.x;
    const float* x = in + (long long)row * DMODEL;
    float v0 = x[tid], v1 = x[tid + 256];
    __shared__ float red[256];
    red[tid] = v0 + v1;
    __syncthreads();
    #pragma unroll
    for (int s = 128; s > 0; s >>= 1) {
        if (tid < s) red[tid] += red[tid + s];
        __syncthreads();
    }
    float mu = red[0] * (1.0f / DMODEL);
    __syncthreads();
    float d0 = v0 - mu, d1 = v1 - mu;
    red[tid] = d0 * d0 + d1 * d1;
    __syncthreads();
    #pragma unroll
    for (int s = 128; s > 0; s >>= 1) {
        if (tid < s) red[tid] += red[tid + s];
        __syncthreads();
    }
    float rstd = rsqrtf(red[0] * (1.0f / DMODEL) + 1e-5f);
    long long base = (long long)row * DMODEL;
    float y0 = d0 * rstd * g[tid] + b[tid];
    float y1 = d1 * rstd * g[tid + 256] + b[tid + 256];
    __nv_bfloat16 h0 = __float2bfloat16(y0);
    __nv_bfloat16 h1 = __float2bfloat16(y1);
    oh[base + tid] = h0;
    ol[base + tid] = __float2bfloat16(y0 - __bfloat162float(h0));
    oh[base + tid + 256] = h1;
    ol[base + tid + 256] = __float2bfloat16(y1 - __bfloat162float(h1));
}

// ---------------- causal attention (f32 in, bf16-split out) ----------------
__global__ __launch_bounds__(128) void attn_k(const float* __restrict__ q,
                                              const float* __restrict__ k,
                                              const float* __restrict__ v,
                                              __nv_bfloat16* __restrict__ ch,
                                              __nv_bfloat16* __restrict__ cl) {
    int gid = blockIdx.x;                 // b*H*S + h*S + i
    int i = gid & (SEQ - 1);
    int h = (gid >> 9) & (NHEAD - 1);
    int b = gid >> 12;
    int tid = threadIdx.x;
    int wid = tid >> 5, lid = tid & 31;

    __shared__ float shq[HEADD];
    __shared__ float sc[SEQ];
    __shared__ float red[128];
    __shared__ float racc[4][64];

    const long long rowbase = (long long)(b * SEQ + i) * DMODEL + h * HEADD;
    if (tid < HEADD) shq[tid] = q[rowbase + tid];
    __syncthreads();

    const float inv_scale = 0.125f;
    float lmax = -1e30f;
    for (int j = tid; j <= i; j += 128) {
        const float4* kr = reinterpret_cast<const float4*>(k + (long long)(b * SEQ + j) * DMODEL + h * HEADD);
        const float4* qr = reinterpret_cast<const float4*>(shq);
        float d = 0.0f;
        #pragma unroll
        for (int c = 0; c < 16; c++) {
            float4 kv = kr[c];
            float4 qv = qr[c];
            d += qv.x * kv.x + qv.y * kv.y + qv.z * kv.z + qv.w * kv.w;
        }
        d *= inv_scale;
        sc[j] = d;
        lmax = fmaxf(lmax, d);
    }
    red[tid] = lmax;
    __syncthreads();
    #pragma unroll
    for (int s = 64; s > 0; s >>= 1) {
        if (tid < s) red[tid] = fmaxf(red[tid], red[tid + s]);
        __syncthreads();
    }
    float mx = red[0];
    __syncthreads();
    float lsum = 0.0f;
    for (int j = tid; j <= i; j += 128) {
        float e = __expf(sc[j] - mx);
        sc[j] = e;
        lsum += e;
    }
    red[tid] = lsum;
    __syncthreads();
    #pragma unroll
    for (int s = 64; s > 0; s >>= 1) {
        if (tid < s) red[tid] += red[tid + s];
        __syncthreads();
    }
    float inv_sum = 1.0f / red[0];
    __syncthreads();

    float a0 = 0.0f, a1 = 0.0f;
    for (int j = wid; j <= i; j += 4) {
        float e = sc[j];
        const float* vr = v + (long long)(b * SEQ + j) * DMODEL + h * HEADD;
        a0 += e * vr[lid];
        a1 += e * vr[lid + 32];
    }
    racc[wid][lid] = a0;
    racc[wid][lid + 32] = a1;
    __syncthreads();
    if (tid < HEADD) {
        float s = (racc[0][tid] + racc[1][tid] + racc[2][tid] + racc[3][tid]) * inv_sum;
        __nv_bfloat16 hh = __float2bfloat16(s);
        ch[rowbase + tid] = hh;
        cl[rowbase + tid] = __float2bfloat16(s - __bfloat162float(hh));
    }
}

// ---------------- per-row cross-entropy ----------------
__global__ __launch_bounds__(256) void loss_row_k(const float* __restrict__ logits,
                                                  const void* __restrict__ tr,
                                                  float* __restrict__ rowloss) {
    __shared__ int mode;
    __shared__ float red[256];
    int row = blockIdx.x, tid = threadIdx.x;
    if (tid == 0) mode = detect_i64(tr, BS);
    __syncthreads();
    const float* lr = logits + (long long)row * VOCAB;
    float lmax = -1e30f;
    for (int j = tid; j < VOCAB; j += 256) lmax = fmaxf(lmax, lr[j]);
    red[tid] = lmax;
    __syncthreads();
    #pragma unroll
    for (int s = 128; s > 0; s >>= 1) {
        if (tid < s) red[tid] = fmaxf(red[tid], red[tid + s]);
        __syncthreads();
    }
    float mx = red[0];
    __syncthreads();
    float lsum = 0.0f;
    for (int j = tid; j < VOCAB; j += 256) lsum += expf(lr[j] - mx);
    red[tid] = lsum;
    __syncthreads();
    #pragma unroll
    for (int s = 128; s > 0; s >>= 1) {
        if (tid < s) red[tid] += red[tid + s];
        __syncthreads();
    }
    if (tid == 0) {
        long long t = load_index(tr, row, mode);
        rowloss[row] = -(lr[t] - mx - logf(red[0]));
    }
}

__global__ __launch_bounds__(1024) void loss_reduce_k(const float* __restrict__ rowloss,
                                                      float* __restrict__ out) {
    __shared__ float red[1024];
    int tid = threadIdx.x;
    red[tid] = rowloss[tid] + rowloss[tid + 1024] + rowloss[tid + 2048] + rowloss[tid + 3072];
    __syncthreads();
    #pragma unroll
    for (int s = 512; s > 0; s >>= 1) {
        if (tid < s) red[tid] += red[tid + s];
        __syncthreads();
    }
    if (tid == 0) out[0] = red[0] * (1.0f / BS);
}

// ---------------- host launcher ----------------
extern "C" void kernel_launch(void* const* d_in, const int* in_sizes, int n_in,
                              void* d_out, int out_size) {
    (void)in_sizes; (void)n_in;
    const void*  x       = d_in[0];
    const void*  targets = d_in[1];
    const float* te   = (const float*)d_in[2];
    const float* pe   = (const float*)d_in[3];
    const float* ln1g = (const float*)d_in[4];
    const float* ln1b = (const float*)d_in[5];
    const float* Wq   = (const float*)d_in[6];
    const float* bq   = (const float*)d_in[7];
    const float* Wk   = (const float*)d_in[8];
    const float* bk   = (const float*)d_in[9];
    const float* Wv   = (const float*)d_in[10];
    const float* bv   = (const float*)d_in[11];
    const float* Wo   = (const float*)d_in[12];
    const float* bo   = (const float*)d_in[13];
    const float* ln2g = (const float*)d_in[14];
    const float* ln2b = (const float*)d_in[15];
    const float* W1   = (const float*)d_in[16];
    const float* b1   = (const float*)d_in[17];
    const float* W2   = (const float*)d_in[18];
    const float* b2   = (const float*)d_in[19];
    const float* lnfg = (const float*)d_in[20];
    const float* lnfb = (const float*)d_in[21];
    float* out = (float*)d_out;

    float *p_h, *p_q, *p_k, *p_v, *p_rowloss, *p_logits;
    __nv_bfloat16 *p_xnh, *p_xnl, *p_ctxh, *p_ctxl, *p_ffh, *p_ffl, *p_wbuf, *p_emb;
    cudaGetSymbolAddress((void**)&p_h, g_h);
    cudaGetSymbolAddress((void**)&p_q, g_q);
    cudaGetSymbolAddress((void**)&p_k, g_k);
    cudaGetSymbolAddress((void**)&p_v, g_v);
    cudaGetSymbolAddress((void**)&p_rowloss, g_rowloss);
    cudaGetSymbolAddress((void**)&p_logits, g_logits_scratch);
    cudaGetSymbolAddress((void**)&p_xnh, g_xnh);
    cudaGetSymbolAddress((void**)&p_xnl, g_xnl);
    cudaGetSymbolAddress((void**)&p_ctxh, g_ctxh);
    cudaGetSymbolAddress((void**)&p_ctxl, g_ctxl);
    cudaGetSymbolAddress((void**)&p_ffh, g_ffh);
    cudaGetSymbolAddress((void**)&p_ffl, g_ffl);
    cudaGetSymbolAddress((void**)&p_wbuf, g_wbuf);
    cudaGetSymbolAddress((void**)&p_emb, g_emb);
    __nv_bfloat16* p_embh = p_emb;
    __nv_bfloat16* p_embl = p_emb + (size_t)VPAD * DMODEL;

    cudaFuncSetAttribute(gemm_bf<0>, cudaFuncAttributeMaxDynamicSharedMemorySize, GEMM_SMEM);
    cudaFuncSetAttribute(gemm_bf<1>, cudaFuncAttributeMaxDynamicSharedMemorySize, GEMM_SMEM);
    cudaFuncSetAttribute(gemm_bf<2>, cudaFuncAttributeMaxDynamicSharedMemorySize, GEMM_SMEM);
    cudaFuncSetAttribute(gemm_bf<3>, cudaFuncAttributeMaxDynamicSharedMemorySize, GEMM_SMEM);

    // weight/emb conversion (every call; deterministic)
    wsplit_qkvo_k<<<dim3(16, 16, 24), dim3(32, 8)>>>(Wq, Wk, Wv, Wo, p_wbuf);
    wsplit_w1_k<<<dim3(64, 16, 6), dim3(32, 8)>>>(W1, p_wbuf);
    wsplit_w2_k<<<dim3(16, 64, 6), dim3(32, 8)>>>(W2, p_wbuf);
    embsplit_k<<<4096, 256>>>(te, p_embh, p_embl);

    embed_k<<<BS, 256>>>(x, te, pe, p_h);

    dim3 gDD(BS / 128, DMODEL / 128);   // (32, 4)
    dim3 gDF(BS / 128, FFDIM / 128);    // (32, 16)

    for (int l = 0; l < NLAYER; l++) {
        __nv_bfloat16* wl = p_wbuf + (size_t)l * WL_STRIDE;
        __nv_bfloat16* wqh = wl;
        __nv_bfloat16* wkh = wl + 2 * (size_t)DDSZ;
        __nv_bfloat16* wvh = wl + 4 * (size_t)DDSZ;
        __nv_bfloat16* woh = wl + 6 * (size_t)DDSZ;
        __nv_bfloat16* w1h = wl + QKVO_TOT;
        __nv_bfloat16* w2h = wl + QKVO_TOT + 2 * (size_t)DFSZ;

        ln_k<<<BS, 256>>>(p_h, ln1g + l * DMODEL, ln1b + l * DMODEL, p_xnh, p_xnl);
        gemm_bf<0><<<gDD, 256, GEMM_SMEM>>>(p_xnh, p_xnl, wqh, wqh + DDSZ, bq + l * DMODEL,
                                            nullptr, p_q, nullptr, nullptr, BS, DMODEL, DMODEL);
        gemm_bf<0><<<gDD, 256, GEMM_SMEM>>>(p_xnh, p_xnl, wkh, wkh + DDSZ, bk + l * DMODEL,
                                            nullptr, p_k, nullptr, nullptr, BS, DMODEL, DMODEL);
        gemm_bf<0><<<gDD, 256, GEMM_SMEM>>>(p_xnh, p_xnl, wvh, wvh + DDSZ, bv + l * DMODEL,
                                            nullptr, p_v, nullptr, nullptr, BS, DMODEL, DMODEL);
        attn_k<<<BATCH * NHEAD * SEQ, 128>>>(p_q, p_k, p_v, p_ctxh, p_ctxl);
        gemm_bf<1><<<gDD, 256, GEMM_SMEM>>>(p_ctxh, p_ctxl, woh, woh + DDSZ, bo + l * DMODEL,
                                            p_h, p_h, nullptr, nullptr, BS, DMODEL, DMODEL);
        ln_k<<<BS, 256>>>(p_h, ln2g + l * DMODEL, ln2b + l * DMODEL, p_xnh, p_xnl);
        gemm_bf<2><<<gDF, 256, GEMM_SMEM>>>(p_xnh, p_xnl, w1h, w1h + DFSZ, b1 + l * FFDIM,
                                            nullptr, nullptr, p_ffh, p_ffl, BS, FFDIM, DMODEL);
        gemm_bf<1><<<gDD, 256, GEMM_SMEM>>>(p_ffh, p_ffl, w2h, w2h + DFSZ, b2 + l * DMODEL,
                                            p_h, p_h, nullptr, nullptr, BS, DMODEL, FFDIM);
    }

    ln_k<<<BS, 256>>>(p_h, lnfg, lnfb, p_xnh, p_xnl);

    float* logits = ((long long)out_size >= NLOG) ? out : p_logits;
    dim3 gLOG(BS / 128, VPAD / 128);   // (32, 393)
    gemm_bf<3><<<gLOG, 256, GEMM_SMEM>>>(p_xnh, p_xnl, p_embh, p_embl, nullptr,
                                         nullptr, logits, nullptr, nullptr, BS, VOCAB, DMODEL);

    loss_row_k<<<BS, 256>>>(logits, targets, p_rowloss);
    if ((long long)out_size > NLOG) {
        loss_reduce_k<<<1, 1024>>>(p_rowloss, out + NLOG);
    } else if ((long long)out_size < NLOG && out_size >= 1) {
        loss_reduce_k<<<1, 1024>>>(p_rowloss, out + (out_size - 1));
    }
}

// round 4
// speedup vs baseline: 3.1823x; 1.7529x over previous
#include <cuda_runtime.h>
#include <cuda_bf16.h>
#include <math.h>
#include <stdint.h>

// ---------------- model constants ----------------
#define BATCH  8
#define SEQ    512
#define DMODEL 512
#define NHEAD  8
#define HEADD  64
#define FFDIM  2048
#define NLAYER 6
#define VOCAB  50257
#define VPAD   50304                  // 393*128
#define BS     (BATCH*SEQ)            // 4096 rows
static const long long NLOG = (long long)BS * VOCAB;  // 205,852,672

// converted-weight layout (bf16), per layer
#define DDSZ   (DMODEL*DMODEL)
#define DFSZ   (DMODEL*FFDIM)
#define QKVO_TOT (4*2*DDSZ)
#define WL_STRIDE (QKVO_TOT + 2*DFSZ + 2*DFSZ)

// ---------------- device scratch ----------------
__device__ float g_h[BS * DMODEL];
__device__ float g_rowloss[BS];
__device__ float g_logits_scratch[(size_t)BS * VOCAB];
__device__ __nv_bfloat16 g_xnh[BS * DMODEL];
__device__ __nv_bfloat16 g_xnl[BS * DMODEL];
__device__ __nv_bfloat16 g_qh[BS * DMODEL];
__device__ __nv_bfloat16 g_ql[BS * DMODEL];
__device__ __nv_bfloat16 g_kh[BS * DMODEL];
__device__ __nv_bfloat16 g_kl[BS * DMODEL];
__device__ __nv_bfloat16 g_vh[BS * DMODEL];
__device__ __nv_bfloat16 g_vl[BS * DMODEL];
__device__ __nv_bfloat16 g_ctxh[BS * DMODEL];
__device__ __nv_bfloat16 g_ctxl[BS * DMODEL];
__device__ __nv_bfloat16 g_ffh[BS * FFDIM];
__device__ __nv_bfloat16 g_ffl[BS * FFDIM];
__device__ __nv_bfloat16 g_wbuf[(size_t)WL_STRIDE * NLAYER];
__device__ __nv_bfloat16 g_emb[2 * (size_t)VPAD * DMODEL];

// ================= PTX helpers =================
__device__ __forceinline__ uint32_t smem_to_u32(const void* smem_ptr) {
    uint32_t addr;
    asm("{ .reg .u64 tmp; cvta.to.shared.u64 tmp, %1; cvt.u32.u64 %0, tmp; }"
        : "=r"(addr) : "l"(smem_ptr));
    return addr;
}
__device__ __forceinline__ void cp16(uint32_t d, const void* s, int sz) {
    asm volatile("cp.async.cg.shared.global [%0], [%1], 16, %2;\n"
                 :: "r"(d), "l"(s), "r"(sz) : "memory");
}
__device__ __forceinline__ void cp_commit() {
    asm volatile("cp.async.commit_group;\n" ::: "memory");
}
__device__ __forceinline__ void cp_wait0() {
    asm volatile("cp.async.wait_group 0;\n" ::: "memory");
}
__device__ __forceinline__ void cp_wait1() {
    asm volatile("cp.async.wait_group 1;\n" ::: "memory");
}
#define LDSM4(r, addr) \
    asm volatile("ldmatrix.sync.aligned.m8n8.x4.shared.b16 {%0,%1,%2,%3}, [%4];" \
        : "=r"((r)[0]), "=r"((r)[1]), "=r"((r)[2]), "=r"((r)[3]) : "r"(addr))
#define MMA16816(c, a, b0, b1) \
    asm volatile("mma.sync.aligned.m16n8k16.row.col.f32.bf16.bf16.f32 " \
        "{%0,%1,%2,%3}, {%4,%5,%6,%7}, {%8,%9}, {%0,%1,%2,%3};" \
        : "+f"((c)[0]), "+f"((c)[1]), "+f"((c)[2]), "+f"((c)[3]) \
        : "r"((a)[0]), "r"((a)[1]), "r"((a)[2]), "r"((a)[3]), "r"(b0), "r"(b1))

// ---------------- GEMM smem layout ----------------
#define TB 16384
#define STAGE_BYTES (4*TB)
#define SMEM_OFF 1024
#define GEMM_SMEM (SMEM_OFF + 2*STAGE_BYTES)

__device__ __forceinline__ void copy_stage(uint32_t st,
        const __nv_bfloat16* __restrict__ Ahi, const __nv_bfloat16* __restrict__ Alo,
        const __nv_bfloat16* __restrict__ Bhi, const __nv_bfloat16* __restrict__ Blo,
        int bm, int bn, int k0, int K, int N, int tid) {
    #pragma unroll
    for (int it = 0; it < 4; it++) {
        int idx = tid + it * 256;
        int row = idx >> 3, c = idx & 7;
        uint32_t d = st + row * 128 + ((c ^ (row & 7)) << 4);
        size_t so = (size_t)(bm + row) * K + k0 + c * 8;
        cp16(d, Ahi + so, 16);
        cp16(d + TB, Alo + so, 16);
    }
    #pragma unroll
    for (int it = 0; it < 4; it++) {
        int idx = tid + it * 256;
        int row = idx >> 3, c = idx & 7;
        int n = bn + row;
        int sz = (n < N) ? 16 : 0;
        uint32_t d = st + 2 * TB + row * 128 + ((c ^ (row & 7)) << 4);
        size_t so = (size_t)n * K + k0 + c * 8;
        cp16(d, Bhi + so, sz);
        cp16(d + TB, Blo + so, sz);
    }
}

// epilogue: 0=bias->f32, 1=bias+res->f32, 2=bias+gelu->bf16 split, 3=plain f32, 4=bias->bf16 split
template <int EPI>
__device__ __forceinline__ void emit_one(float x, size_t off, int col,
        const float* __restrict__ bias, const float* __restrict__ res,
        float* __restrict__ C, __nv_bfloat16* __restrict__ Chi, __nv_bfloat16* __restrict__ Clo) {
    if (EPI == 0 || EPI == 1 || EPI == 2 || EPI == 4) x += __ldg(bias + col);
    if (EPI == 2) x = 0.5f * x * (1.0f + erff(x * 0.70710678118654752440f));
    if (EPI == 1) x += res[off];
    if (EPI == 2 || EPI == 4) {
        __nv_bfloat16 h = __float2bfloat16(x);
        Chi[off] = h;
        Clo[off] = __float2bfloat16(x - __bfloat162float(h));
    } else {
        C[off] = x;
    }
}

// ---------------- GEMM: C[M,N] = (Ahi+Alo)(Bhi+Blo)^T split-compensated ----------------
template <int EPI>
__global__ void __launch_bounds__(256, 1)
gemm_bf(const __nv_bfloat16* __restrict__ Ahi, const __nv_bfloat16* __restrict__ Alo,
        const __nv_bfloat16* __restrict__ Bhi, const __nv_bfloat16* __restrict__ Blo,
        const float* __restrict__ bias, const float* __restrict__ res,
        float* __restrict__ C, __nv_bfloat16* __restrict__ Chi, __nv_bfloat16* __restrict__ Clo,
        int M, int N, int K) {
    extern __shared__ char smem[];
    const int tid = threadIdx.x;
    const int bm = blockIdx.x * 128;
    const int bn = blockIdx.y * 128;
    const int nc = K >> 6;

    const uint32_t tiles = smem_to_u32(smem) + SMEM_OFF;
    const int lane = tid & 31;
    const int wid = tid >> 5;
    const int wm = (wid & 3) << 5;
    const int wn = (wid >> 2) << 6;
    const int mi = lane >> 3;
    const int lrow = lane & 7;

    float acc[2][8][4];
    #pragma unroll
    for (int i = 0; i < 2; i++)
        #pragma unroll
        for (int j = 0; j < 8; j++)
            #pragma unroll
            for (int t = 0; t < 4; t++) acc[i][j][t] = 0.0f;

    copy_stage(tiles, Ahi, Alo, Bhi, Blo, bm, bn, 0, K, N, tid);
    cp_commit();

    for (int c = 0; c < nc; c++) {
        if (c + 1 < nc) {
            copy_stage(tiles + ((c + 1) & 1) * STAGE_BYTES, Ahi, Alo, Bhi, Blo,
                       bm, bn, (c + 1) << 6, K, N, tid);
            cp_commit();
            cp_wait1();
        } else {
            cp_wait0();
        }
        __syncthreads();

        const uint32_t st = tiles + (c & 1) * STAGE_BYTES;
        #pragma unroll
        for (int s = 0; s < 4; s++) {
            const int cb = (s << 5) + ((mi >> 1) << 4);
            uint32_t ahi[2][4], alo[2][4], bhi[4][4], blo[4][4];
            #pragma unroll
            for (int i = 0; i < 2; i++) {
                int r = wm + (i << 4) + ((mi & 1) << 3) + lrow;
                uint32_t a = st + r * 128 + (cb ^ ((r & 7) << 4));
                LDSM4(ahi[i], a);
                LDSM4(alo[i], a + TB);
            }
            #pragma unroll
            for (int j2 = 0; j2 < 4; j2++) {
                int r = wn + (j2 << 4) + ((mi & 1) << 3) + lrow;
                uint32_t a = st + 2 * TB + r * 128 + (cb ^ ((r & 7) << 4));
                LDSM4(bhi[j2], a);
                LDSM4(blo[j2], a + TB);
            }
            #pragma unroll
            for (int i = 0; i < 2; i++)
                #pragma unroll
                for (int j2 = 0; j2 < 4; j2++) {
                    MMA16816(acc[i][2 * j2],     ahi[i], bhi[j2][0], bhi[j2][2]);
                    MMA16816(acc[i][2 * j2 + 1], ahi[i], bhi[j2][1], bhi[j2][3]);
                }
            #pragma unroll
            for (int i = 0; i < 2; i++)
                #pragma unroll
                for (int j2 = 0; j2 < 4; j2++) {
                    MMA16816(acc[i][2 * j2],     alo[i], bhi[j2][0], bhi[j2][2]);
                    MMA16816(acc[i][2 * j2 + 1], alo[i], bhi[j2][1], bhi[j2][3]);
                }
            #pragma unroll
            for (int i = 0; i < 2; i++)
                #pragma unroll
                for (int j2 = 0; j2 < 4; j2++) {
                    MMA16816(acc[i][2 * j2],     ahi[i], blo[j2][0], blo[j2][2]);
                    MMA16816(acc[i][2 * j2 + 1], ahi[i], blo[j2][1], blo[j2][3]);
                }
        }
        __syncthreads();
    }

    #pragma unroll
    for (int i = 0; i < 2; i++) {
        int row = bm + wm + (i << 4) + (lane >> 2);
        size_t base = (size_t)row * N;
        size_t base8 = base + (size_t)8 * N;
        #pragma unroll
        for (int j = 0; j < 8; j++) {
            int col = bn + wn + (j << 3) + ((lane & 3) << 1);
            if (col < N)     emit_one<EPI>(acc[i][j][0], base + col, col, bias, res, C, Chi, Clo);
            if (col + 1 < N) emit_one<EPI>(acc[i][j][1], base + col + 1, col + 1, bias, res, C, Chi, Clo);
            if (col < N)     emit_one<EPI>(acc[i][j][2], base8 + col, col, bias, res, C, Chi, Clo);
            if (col + 1 < N) emit_one<EPI>(acc[i][j][3], base8 + col + 1, col + 1, bias, res, C, Chi, Clo);
        }
    }
}

// ---------------- flash attention (mma.sync, split-compensated) ----------------
// Block = (q-tile 128, b*h). 8 warps x 16 rows. K tiles: [j,64] K-major like GEMM B.
// V transposed into SMEM as [d=64][j=128] rows of 256B (swizzled), PV uses GEMM B pattern.
#define ATT_SMEM (6*16384)
__global__ void __launch_bounds__(256, 1)
fattn_k(const __nv_bfloat16* __restrict__ qh, const __nv_bfloat16* __restrict__ ql,
        const __nv_bfloat16* __restrict__ kh, const __nv_bfloat16* __restrict__ kl,
        const __nv_bfloat16* __restrict__ vh, const __nv_bfloat16* __restrict__ vl,
        __nv_bfloat16* __restrict__ ch, __nv_bfloat16* __restrict__ cl) {
    extern __shared__ char smx[];
    const uint32_t sQ = smem_to_u32(smx);
    const uint32_t sK = sQ + 2 * 16384;
    const uint32_t sV = sQ + 4 * 16384;
    const int tid = threadIdx.x;
    const int lane = tid & 31, wid = tid >> 5;
    const int qt = blockIdx.x;
    const int bh = blockIdx.y;
    const int b = bh >> 3, h = bh & 7;
    const int tokQ = b * SEQ + qt * 128;
    const int ho = h * HEADD;
    const int mi = lane >> 3, lrow = lane & 7;
    const int wm = wid * 16;
    const int rB = ((mi & 1) << 3) + lrow;

    // ---- load Q tile (hi/lo)
    #pragma unroll
    for (int it = 0; it < 4; it++) {
        int idx = tid + it * 256;
        int r = idx >> 3, c = idx & 7;
        uint32_t d = sQ + r * 128 + ((c ^ (r & 7)) << 4);
        size_t so = (size_t)(tokQ + r) * DMODEL + ho + c * 8;
        cp16(d, qh + so, 16);
        cp16(d + 16384, ql + so, 16);
    }
    cp_commit();
    cp_wait0();
    __syncthreads();

    // Q A-frags (per warp: 16 rows x 64 k), hi and lo
    uint32_t aq[4][4], aql[4][4];
    {
        int r = wm + rB;
        #pragma unroll
        for (int s = 0; s < 4; s++) {
            uint32_t addr = sQ + r * 128 + ((((s << 5) + ((mi >> 1) << 4))) ^ ((r & 7) << 4));
            LDSM4(aq[s], addr);
            LDSM4(aql[s], addr + 16384);
        }
    }

    float oacc[8][4];
    #pragma unroll
    for (int f = 0; f < 8; f++)
        #pragma unroll
        for (int t = 0; t < 4; t++) oacc[f][t] = 0.0f;
    float mr0 = -1e30f, mr1 = -1e30f, lr0 = 0.0f, lr1 = 0.0f;
    const int myr0 = wm + (lane >> 2);
    const int myr1 = myr0 + 8;

    for (int jt = 0; jt <= qt; jt++) {
        __syncthreads();   // previous tile's compute must finish before overwrite
        const int tokJ = b * SEQ + jt * 128;
        // K tile (hi/lo) via cp.async
        #pragma unroll
        for (int it = 0; it < 4; it++) {
            int idx = tid + it * 256;
            int r = idx >> 3, c = idx & 7;
            uint32_t d = sK + r * 128 + ((c ^ (r & 7)) << 4);
            size_t so = (size_t)(tokJ + r) * DMODEL + ho + c * 8;
            cp16(d, kh + so, 16);
            cp16(d + 16384, kl + so, 16);
        }
        // V transpose into sV: [d][j] rows of 256B, granule-swizzled
        #pragma unroll
        for (int it = 0; it < 4; it++) {
            int task = tid + it * 256;
            int j = task >> 3, c = task & 7;
            size_t so = (size_t)(tokJ + j) * DMODEL + ho + c * 8;
            uint4 v4h = *reinterpret_cast<const uint4*>(vh + so);
            uint4 v4l = *reinterpret_cast<const uint4*>(vl + so);
            const uint32_t* wh = &v4h.x;
            const uint32_t* wl = &v4l.x;
            #pragma unroll
            for (int i = 0; i < 8; i++) {
                int dd = c * 8 + i;
                uint32_t off = dd * 256 + ((((uint32_t)(j >> 3) ^ (uint32_t)(dd & 7)) << 4)) + (j & 7) * 2;
                uint16_t hv = (uint16_t)(wh[i >> 1] >> ((i & 1) * 16));
                uint16_t lv = (uint16_t)(wl[i >> 1] >> ((i & 1) * 16));
                asm volatile("st.shared.u16 [%0], %1;" :: "r"(sV + off), "h"(hv));
                asm volatile("st.shared.u16 [%0], %1;" :: "r"(sV + 16384 + off), "h"(lv));
            }
        }
        cp_commit();
        cp_wait0();
        __syncthreads();

        // ---- S = Q K^T (3-pass split), per warp 16x128
        float facc[16][4];
        #pragma unroll
        for (int f = 0; f < 16; f++)
            #pragma unroll
            for (int t = 0; t < 4; t++) facc[f][t] = 0.0f;
        #pragma unroll
        for (int g = 0; g < 8; g++) {
            int r = g * 16 + rB;
            #pragma unroll
            for (int s = 0; s < 4; s++) {
                uint32_t kb[4], kbl[4];
                uint32_t addr = sK + r * 128 + ((((s << 5) + ((mi >> 1) << 4))) ^ ((r & 7) << 4));
                LDSM4(kb, addr);
                LDSM4(kbl, addr + 16384);
                MMA16816(facc[2 * g],     aq[s],  kb[0],  kb[2]);
                MMA16816(facc[2 * g + 1], aq[s],  kb[1],  kb[3]);
                MMA16816(facc[2 * g],     aql[s], kb[0],  kb[2]);
                MMA16816(facc[2 * g + 1], aql[s], kb[1],  kb[3]);
                MMA16816(facc[2 * g],     aq[s],  kbl[0], kbl[2]);
                MMA16816(facc[2 * g + 1], aq[s],  kbl[1], kbl[3]);
            }
        }
        // scale + causal mask
        const float scl = 0.125f;
        #pragma unroll
        for (int f = 0; f < 16; f++) {
            int c0 = f * 8 + 2 * (lane & 3);
            facc[f][0] *= scl; facc[f][1] *= scl;
            facc[f][2] *= scl; facc[f][3] *= scl;
            if (jt == qt) {
                if (c0     > myr0) facc[f][0] = -1e30f;
                if (c0 + 1 > myr0) facc[f][1] = -1e30f;
                if (c0     > myr1) facc[f][2] = -1e30f;
                if (c0 + 1 > myr1) facc[f][3] = -1e30f;
            }
        }
        // row max (quad shuffle)
        float m0 = -1e30f, m1 = -1e30f;
        #pragma unroll
        for (int f = 0; f < 16; f++) {
            m0 = fmaxf(m0, fmaxf(facc[f][0], facc[f][1]));
            m1 = fmaxf(m1, fmaxf(facc[f][2], facc[f][3]));
        }
        m0 = fmaxf(m0, __shfl_xor_sync(0xffffffffu, m0, 1));
        m0 = fmaxf(m0, __shfl_xor_sync(0xffffffffu, m0, 2));
        m1 = fmaxf(m1, __shfl_xor_sync(0xffffffffu, m1, 1));
        m1 = fmaxf(m1, __shfl_xor_sync(0xffffffffu, m1, 2));
        float nm0 = fmaxf(mr0, m0), nm1 = fmaxf(mr1, m1);
        float al0 = __expf(mr0 - nm0), al1 = __expf(mr1 - nm1);
        mr0 = nm0; mr1 = nm1;
        #pragma unroll
        for (int f = 0; f < 8; f++) {
            oacc[f][0] *= al0; oacc[f][1] *= al0;
            oacc[f][2] *= al1; oacc[f][3] *= al1;
        }
        // P = exp(S - m), pack to A-frags hi/lo
        float s0 = 0.0f, s1 = 0.0f;
        uint32_t pah[8][4], pal[8][4];
        #pragma unroll
        for (int f = 0; f < 16; f++) {
            float p0 = __expf(facc[f][0] - nm0);
            float p1 = __expf(facc[f][1] - nm0);
            float p2 = __expf(facc[f][2] - nm1);
            float p3 = __expf(facc[f][3] - nm1);
            s0 += p0 + p1;
            s1 += p2 + p3;
            __nv_bfloat162 hp = __floats2bfloat162_rn(p0, p1);
            float2 hf = __bfloat1622float2(hp);
            __nv_bfloat162 lp = __floats2bfloat162_rn(p0 - hf.x, p1 - hf.y);
            __nv_bfloat162 hq = __floats2bfloat162_rn(p2, p3);
            float2 hg = __bfloat1622float2(hq);
            __nv_bfloat162 lq = __floats2bfloat162_rn(p2 - hg.x, p3 - hg.y);
            int ks = f >> 1, half = f & 1;
            pah[ks][2 * half]     = *reinterpret_cast<uint32_t*>(&hp);
            pah[ks][2 * half + 1] = *reinterpret_cast<uint32_t*>(&hq);
            pal[ks][2 * half]     = *reinterpret_cast<uint32_t*>(&lp);
            pal[ks][2 * half + 1] = *reinterpret_cast<uint32_t*>(&lq);
        }
        s0 += __shfl_xor_sync(0xffffffffu, s0, 1);
        s0 += __shfl_xor_sync(0xffffffffu, s0, 2);
        s1 += __shfl_xor_sync(0xffffffffu, s1, 1);
        s1 += __shfl_xor_sync(0xffffffffu, s1, 2);
        lr0 = lr0 * al0 + s0;
        lr1 = lr1 * al1 + s1;
        // ---- O += P V (3-pass split)
        #pragma unroll
        for (int ks = 0; ks < 8; ks++) {
            #pragma unroll
            for (int g2 = 0; g2 < 4; g2++) {
                uint32_t vb[4], vbl[4];
                int r = g2 * 16 + rB;
                uint32_t addr = sV + r * 256 + ((((ks << 5) + ((mi >> 1) << 4))) ^ ((r & 7) << 4));
                LDSM4(vb, addr);
                LDSM4(vbl, addr + 16384);
                MMA16816(oacc[2 * g2],     pah[ks], vb[0],  vb[2]);
                MMA16816(oacc[2 * g2 + 1], pah[ks], vb[1],  vb[3]);
                MMA16816(oacc[2 * g2],     pal[ks], vb[0],  vb[2]);
                MMA16816(oacc[2 * g2 + 1], pal[ks], vb[1],  vb[3]);
                MMA16816(oacc[2 * g2],     pah[ks], vbl[0], vbl[2]);
                MMA16816(oacc[2 * g2 + 1], pah[ks], vbl[1], vbl[3]);
            }
        }
    }

    // ---- normalize + write split ctx
    float inv0 = 1.0f / lr0, inv1 = 1.0f / lr1;
    size_t t0 = (size_t)(tokQ + myr0) * DMODEL + ho;
    size_t t1 = t0 + (size_t)8 * DMODEL;
    #pragma unroll
    for (int f = 0; f < 8; f++) {
        int dc = f * 8 + 2 * (lane & 3);
        float x0 = oacc[f][0] * inv0, x1 = oacc[f][1] * inv0;
        float x2 = oacc[f][2] * inv1, x3 = oacc[f][3] * inv1;
        __nv_bfloat162 h01 = __floats2bfloat162_rn(x0, x1);
        float2 hf = __bfloat1622float2(h01);
        __nv_bfloat162 l01 = __floats2bfloat162_rn(x0 - hf.x, x1 - hf.y);
        __nv_bfloat162 h23 = __floats2bfloat162_rn(x2, x3);
        float2 hg = __bfloat1622float2(h23);
        __nv_bfloat162 l23 = __floats2bfloat162_rn(x2 - hg.x, x3 - hg.y);
        *reinterpret_cast<uint32_t*>(ch + t0 + dc) = *reinterpret_cast<uint32_t*>(&h01);
        *reinterpret_cast<uint32_t*>(cl + t0 + dc) = *reinterpret_cast<uint32_t*>(&l01);
        *reinterpret_cast<uint32_t*>(ch + t1 + dc) = *reinterpret_cast<uint32_t*>(&h23);
        *reinterpret_cast<uint32_t*>(cl + t1 + dc) = *reinterpret_cast<uint32_t*>(&l23);
    }
}

// ---------------- weight transpose + split ----------------
__device__ __forceinline__ void transpose_split(const float* __restrict__ in,
        __nv_bfloat16* __restrict__ hi, __nv_bfloat16* __restrict__ lo, int K, int N) {
    __shared__ float t[32][33];
    int n0 = blockIdx.x << 5, k0 = blockIdx.y << 5;
    int tx = threadIdx.x, ty = threadIdx.y;
    #pragma unroll
    for (int r = 0; r < 4; r++)
        t[ty + 8 * r][tx] = in[(size_t)(k0 + ty + 8 * r) * N + n0 + tx];
    __syncthreads();
    #pragma unroll
    for (int r = 0; r < 4; r++) {
        float v = t[tx][ty + 8 * r];
        size_t o = (size_t)(n0 + ty + 8 * r) * K + k0 + tx;
        __nv_bfloat16 h = __float2bfloat16(v);
        hi[o] = h;
        lo[o] = __float2bfloat16(v - __bfloat162float(h));
    }
}
__global__ void wsplit_qkvo_k(const float* __restrict__ Wq, const float* __restrict__ Wk,
                              const float* __restrict__ Wv, const float* __restrict__ Wo,
                              __nv_bfloat16* __restrict__ wbuf) {
    int z = blockIdx.z, l = z >> 2, m = z & 3;
    const float* W = (m == 0 ? Wq : m == 1 ? Wk : m == 2 ? Wv : Wo) + (size_t)l * DDSZ;
    __nv_bfloat16* hi = wbuf + (size_t)l * WL_STRIDE + (size_t)m * 2 * DDSZ;
    transpose_split(W, hi, hi + DDSZ, DMODEL, DMODEL);
}
__global__ void wsplit_w1_k(const float* __restrict__ W1, __nv_bfloat16* __restrict__ wbuf) {
    int l = blockIdx.z;
    __nv_bfloat16* hi = wbuf + (size_t)l * WL_STRIDE + QKVO_TOT;
    transpose_split(W1 + (size_t)l * DFSZ, hi, hi + DFSZ, DMODEL, FFDIM);
}
__global__ void wsplit_w2_k(const float* __restrict__ W2, __nv_bfloat16* __restrict__ wbuf) {
    int l = blockIdx.z;
    __nv_bfloat16* hi = wbuf + (size_t)l * WL_STRIDE + QKVO_TOT + 2 * (size_t)DFSZ;
    transpose_split(W2 + (size_t)l * DFSZ, hi, hi + DFSZ, FFDIM, DMODEL);
}
__global__ __launch_bounds__(256) void embsplit_k(const float* __restrict__ te,
        __nv_bfloat16* __restrict__ hi, __nv_bfloat16* __restrict__ lo) {
    size_t n = (size_t)VOCAB * DMODEL;
    for (size_t i = (size_t)blockIdx.x * blockDim.x + threadIdx.x; i < n;
         i += (size_t)gridDim.x * blockDim.x) {
        float v = te[i];
        __nv_bfloat16 h = __float2bfloat16(v);
        hi[i] = h;
        lo[i] = __float2bfloat16(v - __bfloat162float(h));
    }
}

// ---------------- helpers ----------------
__device__ __forceinline__ int detect_i64(const void* p, int n) {
    const long long* x = (const long long*)p;
    int c = n < 32 ? n : 32;
    for (int i = 0; i < c; i++) {
        long long v = x[i];
        if (v < 0 || v >= VOCAB) return 0;
    }
    return 1;
}
__device__ __forceinline__ long long load_index(const void* p, int i, int is64) {
    return is64 ? ((const long long*)p)[i] : (long long)((const int*)p)[i];
}

// ---------------- embedding ----------------
__global__ __launch_bounds__(256) void embed_k(const void* __restrict__ xr,
                                               const float* __restrict__ te,
                                               const float* __restrict__ pe,
                                               float* __restrict__ h) {
    __shared__ int mode;
    if (threadIdx.x == 0) mode = detect_i64(xr, BS);
    __syncthreads();
    int pos = blockIdx.x;
    int tid = threadIdx.x;
    long long idx = load_index(xr, pos, mode);
    int s = pos & (SEQ - 1);
    const float* t = te + idx * DMODEL;
    const float* p = pe + (long long)s * DMODEL;
    float* o = h + (long long)pos * DMODEL;
    o[tid]       = t[tid]       + p[tid];
    o[tid + 256] = t[tid + 256] + p[tid + 256];
}

// ---------------- layernorm -> bf16 split ----------------
__global__ __launch_bounds__(256) void ln_k(const float* __restrict__ in,
                                            const float* __restrict__ g,
                                            const float* __restrict__ b,
                                            __nv_bfloat16* __restrict__ oh,
                                            __nv_bfloat16* __restrict__ ol) {
    int row = blockIdx.x;
    int tid = threadIdx.x;
    const float* x = in + (long long)row * DMODEL;
    float v0 = x[tid], v1 = x[tid + 256];
    __shared__ float red[256];
    red[tid] = v0 + v1;
    __syncthreads();
    #pragma unroll
    for (int s = 128; s > 0; s >>= 1) {
        if (tid < s) red[tid] += red[tid + s];
        __syncthreads();
    }
    float mu = red[0] * (1.0f / DMODEL);
    __syncthreads();
    float d0 = v0 - mu, d1 = v1 - mu;
    red[tid] = d0 * d0 + d1 * d1;
    __syncthreads();
    #pragma unroll
    for (int s = 128; s > 0; s >>= 1) {
        if (tid < s) red[tid] += red[tid + s];
        __syncthreads();
    }
    float rstd = rsqrtf(red[0] * (1.0f / DMODEL) + 1e-5f);
    long long base = (long long)row * DMODEL;
    float y0 = d0 * rstd * g[tid] + b[tid];
    float y1 = d1 * rstd * g[tid + 256] + b[tid + 256];
    __nv_bfloat16 h0 = __float2bfloat16(y0);
    __nv_bfloat16 h1 = __float2bfloat16(y1);
    oh[base + tid] = h0;
    ol[base + tid] = __float2bfloat16(y0 - __bfloat162float(h0));
    oh[base + tid + 256] = h1;
    ol[base + tid + 256] = __float2bfloat16(y1 - __bfloat162float(h1));
}

// ---------------- single-pass cross-entropy ----------------
__global__ __launch_bounds__(256) void loss_row_k(const float* __restrict__ logits,
                                                  const void* __restrict__ tr,
                                                  float* __restrict__ rowloss) {
    __shared__ int mode;
    __shared__ float rm[256], rs[256];
    int row = blockIdx.x, tid = threadIdx.x;
    if (tid == 0) mode = detect_i64(tr, BS);
    __syncthreads();
    const float* lr = logits + (long long)row * VOCAB;
    float m = -1e30f, s = 0.0f;
    for (int j = tid; j < VOCAB; j += 256) {
        float v = lr[j];
        float nm = fmaxf(m, v);
        s = s * __expf(m - nm) + __expf(v - nm);
        m = nm;
    }
    rm[tid] = m;
    rs[tid] = s;
    __syncthreads();
    #pragma unroll
    for (int st = 128; st > 0; st >>= 1) {
        if (tid < st) {
            float ma = rm[tid], mb = rm[tid + st];
            float nm = fmaxf(ma, mb);
            rs[tid] = rs[tid] * __expf(ma - nm) + rs[tid + st] * __expf(mb - nm);
            rm[tid] = nm;
        }
        __syncthreads();
    }
    if (tid == 0) {
        long long t = load_index(tr, row, mode);
        rowloss[row] = -(lr[t] - rm[0] - logf(rs[0]));
    }
}

__global__ __launch_bounds__(1024) void loss_reduce_k(const float* __restrict__ rowloss,
                                                      float* __restrict__ out) {
    __shared__ float red[1024];
    int tid = threadIdx.x;
    red[tid] = rowloss[tid] + rowloss[tid + 1024] + rowloss[tid + 2048] + rowloss[tid + 3072];
    __syncthreads();
    #pragma unroll
    for (int s = 512; s > 0; s >>= 1) {
        if (tid < s) red[tid] += red[tid + s];
        __syncthreads();
    }
    if (tid == 0) out[0] = red[0] * (1.0f / BS);
}

// ---------------- host launcher ----------------
extern "C" void kernel_launch(void* const* d_in, const int* in_sizes, int n_in,
                              void* d_out, int out_size) {
    (void)in_sizes; (void)n_in;
    const void*  x       = d_in[0];
    const void*  targets = d_in[1];
    const float* te   = (const float*)d_in[2];
    const float* pe   = (const float*)d_in[3];
    const float* ln1g = (const float*)d_in[4];
    const float* ln1b = (const float*)d_in[5];
    const float* Wq   = (const float*)d_in[6];
    const float* bq   = (const float*)d_in[7];
    const float* Wk   = (const float*)d_in[8];
    const float* bk   = (const float*)d_in[9];
    const float* Wv   = (const float*)d_in[10];
    const float* bv   = (const float*)d_in[11];
    const float* Wo   = (const float*)d_in[12];
    const float* bo   = (const float*)d_in[13];
    const float* ln2g = (const float*)d_in[14];
    const float* ln2b = (const float*)d_in[15];
    const float* W1   = (const float*)d_in[16];
    const float* b1   = (const float*)d_in[17];
    const float* W2   = (const float*)d_in[18];
    const float* b2   = (const float*)d_in[19];
    const float* lnfg = (const float*)d_in[20];
    const float* lnfb = (const float*)d_in[21];
    float* out = (float*)d_out;

    float *p_h, *p_rowloss, *p_logits;
    __nv_bfloat16 *p_xnh, *p_xnl, *p_qh, *p_ql, *p_kh, *p_kl, *p_vh, *p_vl;
    __nv_bfloat16 *p_ctxh, *p_ctxl, *p_ffh, *p_ffl, *p_wbuf, *p_emb;
    cudaGetSymbolAddress((void**)&p_h, g_h);
    cudaGetSymbolAddress((void**)&p_rowloss, g_rowloss);
    cudaGetSymbolAddress((void**)&p_logits, g_logits_scratch);
    cudaGetSymbolAddress((void**)&p_xnh, g_xnh);
    cudaGetSymbolAddress((void**)&p_xnl, g_xnl);
    cudaGetSymbolAddress((void**)&p_qh, g_qh);
    cudaGetSymbolAddress((void**)&p_ql, g_ql);
    cudaGetSymbolAddress((void**)&p_kh, g_kh);
    cudaGetSymbolAddress((void**)&p_kl, g_kl);
    cudaGetSymbolAddress((void**)&p_vh, g_vh);
    cudaGetSymbolAddress((void**)&p_vl, g_vl);
    cudaGetSymbolAddress((void**)&p_ctxh, g_ctxh);
    cudaGetSymbolAddress((void**)&p_ctxl, g_ctxl);
    cudaGetSymbolAddress((void**)&p_ffh, g_ffh);
    cudaGetSymbolAddress((void**)&p_ffl, g_ffl);
    cudaGetSymbolAddress((void**)&p_wbuf, g_wbuf);
    cudaGetSymbolAddress((void**)&p_emb, g_emb);
    __nv_bfloat16* p_embh = p_emb;
    __nv_bfloat16* p_embl = p_emb + (size_t)VPAD * DMODEL;

    cudaFuncSetAttribute(gemm_bf<0>, cudaFuncAttributeMaxDynamicSharedMemorySize, GEMM_SMEM);
    cudaFuncSetAttribute(gemm_bf<1>, cudaFuncAttributeMaxDynamicSharedMemorySize, GEMM_SMEM);
    cudaFuncSetAttribute(gemm_bf<2>, cudaFuncAttributeMaxDynamicSharedMemorySize, GEMM_SMEM);
    cudaFuncSetAttribute(gemm_bf<3>, cudaFuncAttributeMaxDynamicSharedMemorySize, GEMM_SMEM);
    cudaFuncSetAttribute(gemm_bf<4>, cudaFuncAttributeMaxDynamicSharedMemorySize, GEMM_SMEM);
    cudaFuncSetAttribute(fattn_k, cudaFuncAttributeMaxDynamicSharedMemorySize, ATT_SMEM);

    wsplit_qkvo_k<<<dim3(16, 16, 24), dim3(32, 8)>>>(Wq, Wk, Wv, Wo, p_wbuf);
    wsplit_w1_k<<<dim3(64, 16, 6), dim3(32, 8)>>>(W1, p_wbuf);
    wsplit_w2_k<<<dim3(16, 64, 6), dim3(32, 8)>>>(W2, p_wbuf);
    embsplit_k<<<4096, 256>>>(te, p_embh, p_embl);

    embed_k<<<BS, 256>>>(x, te, pe, p_h);

    dim3 gDD(BS / 128, DMODEL / 128);
    dim3 gDF(BS / 128, FFDIM / 128);
    dim3 gATT(SEQ / 128, BATCH * NHEAD);

    for (int l = 0; l < NLAYER; l++) {
        __nv_bfloat16* wl = p_wbuf + (size_t)l * WL_STRIDE;
        __nv_bfloat16* wqh = wl;
        __nv_bfloat16* wkh = wl + 2 * (size_t)DDSZ;
        __nv_bfloat16* wvh = wl + 4 * (size_t)DDSZ;
        __nv_bfloat16* woh = wl + 6 * (size_t)DDSZ;
        __nv_bfloat16* w1h = wl + QKVO_TOT;
        __nv_bfloat16* w2h = wl + QKVO_TOT + 2 * (size_t)DFSZ;

        ln_k<<<BS, 256>>>(p_h, ln1g + l * DMODEL, ln1b + l * DMODEL, p_xnh, p_xnl);
        gemm_bf<4><<<gDD, 256, GEMM_SMEM>>>(p_xnh, p_xnl, wqh, wqh + DDSZ, bq + l * DMODEL,
                                            nullptr, nullptr, p_qh, p_ql, BS, DMODEL, DMODEL);
        gemm_bf<4><<<gDD, 256, GEMM_SMEM>>>(p_xnh, p_xnl, wkh, wkh + DDSZ, bk + l * DMODEL,
                                            nullptr, nullptr, p_kh, p_kl, BS, DMODEL, DMODEL);
        gemm_bf<4><<<gDD, 256, GEMM_SMEM>>>(p_xnh, p_xnl, wvh, wvh + DDSZ, bv + l * DMODEL,
                                            nullptr, nullptr, p_vh, p_vl, BS, DMODEL, DMODEL);
        fattn_k<<<gATT, 256, ATT_SMEM>>>(p_qh, p_ql, p_kh, p_kl, p_vh, p_vl, p_ctxh, p_ctxl);
        gemm_bf<1><<<gDD, 256, GEMM_SMEM>>>(p_ctxh, p_ctxl, woh, woh + DDSZ, bo + l * DMODEL,
                                            p_h, p_h, nullptr, nullptr, BS, DMODEL, DMODEL);
        ln_k<<<BS, 256>>>(p_h, ln2g + l * DMODEL, ln2b + l * DMODEL, p_xnh, p_xnl);
        gemm_bf<2><<<gDF, 256, GEMM_SMEM>>>(p_xnh, p_xnl, w1h, w1h + DFSZ, b1 + l * FFDIM,
                                            nullptr, nullptr, p_ffh, p_ffl, BS, FFDIM, DMODEL);
        gemm_bf<1><<<gDD, 256, GEMM_SMEM>>>(p_ffh, p_ffl, w2h, w2h + DFSZ, b2 + l * DMODEL,
                                            p_h, p_h, nullptr, nullptr, BS, DMODEL, FFDIM);
    }

    ln_k<<<BS, 256>>>(p_h, lnfg, lnfb, p_xnh, p_xnl);

    float* logits = ((long long)out_size >= NLOG) ? out : p_logits;
    dim3 gLOG(BS / 128, VPAD / 128);
    gemm_bf<3><<<gLOG, 256, GEMM_SMEM>>>(p_xnh, p_xnl, p_embh, p_embl, nullptr,
                                         nullptr, logits, nullptr, nullptr, BS, VOCAB, DMODEL);

    loss_row_k<<<BS, 256>>>(logits, targets, p_rowloss);
    if ((long long)out_size > NLOG) {
        loss_reduce_k<<<1, 1024>>>(p_rowloss, out + NLOG);
    } else if ((long long)out_size < NLOG && out_size >= 1) {
        loss_reduce_k<<<1, 1024>>>(p_rowloss, out + (out_size - 1));
    }
}